// round 5
// baseline (speedup 1.0000x reference)
#include <cuda_runtime.h>
#include <cstdint>

#define T_SEQ  2048
#define BATCH  8
#define DMODEL 1024
#define WIN    64
#define LOG2E  1.4426950408889634f

// Scratch (≈10 MB total)
__device__ float g_M[(size_t)BATCH * DMODEL * WIN];   // M[b][d][j]
__device__ float g_P[(size_t)BATCH * T_SEQ * WIN];    // p_t[j]*log2e per batch
__device__ float g_C[(size_t)BATCH * T_SEQ * WIN];    // coefficients of v_t
__device__ float g_bP[BATCH * WIN];                   // bias term of p

// packed f32x2 helpers
__device__ __forceinline__ void fma2(uint64_t& acc, uint64_t a, uint64_t b) {
    asm("fma.rn.f32x2 %0, %1, %2, %0;" : "+l"(acc) : "l"(a), "l"(b));
}
__device__ __forceinline__ void add2(uint64_t& a, uint64_t b) {
    asm("add.rn.f32x2 %0, %0, %1;" : "+l"(a) : "l"(b));
}
__device__ __forceinline__ float lo2(uint64_t v) {
    return __uint_as_float((uint32_t)v);
}
__device__ __forceinline__ float hi2(uint64_t v) {
    return __uint_as_float((uint32_t)(v >> 32));
}
__device__ __forceinline__ float ex2f(float x) {
    float r; asm("ex2.approx.ftz.f32 %0, %1;" : "=f"(r) : "f"(x)); return r;
}
__device__ __forceinline__ float rcpf(float x) {
    float r; asm("rcp.approx.ftz.f32 %0, %1;" : "=f"(r) : "f"(x)); return r;
}

// ---------------------------------------------------------------------------
// biasP[b][j] = sum_e wq_b[e] * w2[e] * F[b][j][e]
// ---------------------------------------------------------------------------
__global__ __launch_bounds__(256) void bias_p_kernel(
    const float* __restrict__ feat, const float* __restrict__ wqb,
    const float* __restrict__ w2)
{
    const int b = blockIdx.x;
    const int j = threadIdx.x >> 2;
    const int q = threadIdx.x & 3;
    const float* fp = feat + ((size_t)b * T_SEQ + j) * DMODEL + q * 256;
    float s = 0.f;
#pragma unroll 4
    for (int e = 0; e < 256; e += 4) {
        float4 f  = *(const float4*)(fp + e);
        float4 wb = *(const float4*)(wqb + q * 256 + e);
        float4 ww = *(const float4*)(w2 + q * 256 + e);
        s += f.x * wb.x * ww.x + f.y * wb.y * ww.y +
             f.z * wb.z * ww.z + f.w * wb.w * ww.w;
    }
    s += __shfl_xor_sync(0xffffffffu, s, 1);
    s += __shfl_xor_sync(0xffffffffu, s, 2);
    if (q == 0) g_bP[b * WIN + j] = s;
}

// ---------------------------------------------------------------------------
// k1: M[b] = wq @ (F[b,:64]*w2)^T.  Tile 128x64, K=1024.
// ---------------------------------------------------------------------------
__global__ __launch_bounds__(256) void m_kernel(
    const float* __restrict__ wq, const float* __restrict__ w2,
    const float* __restrict__ feat)
{
    __shared__ float As[16][129];
    __shared__ float Bs[16][68];
    const int b  = blockIdx.y;
    const int d0 = blockIdx.x * 128;
    const int tid = threadIdx.x;
    const int ty = tid >> 3, tx = tid & 7;
    const int r0 = ty * 4, j0 = tx * 8;

    float acc[4][8];
#pragma unroll
    for (int i = 0; i < 4; i++)
#pragma unroll
        for (int j = 0; j < 8; j++) acc[i][j] = 0.f;

    for (int e0 = 0; e0 < DMODEL; e0 += 16) {
#pragma unroll
        for (int l = 0; l < 2; l++) {
            int s = tid + l * 256;
            int r = s >> 2, kc = (s & 3) * 4;
            float4 w = *(const float4*)(wq + (size_t)(d0 + r) * DMODEL + e0 + kc);
            As[kc + 0][r] = w.x; As[kc + 1][r] = w.y;
            As[kc + 2][r] = w.z; As[kc + 3][r] = w.w;
        }
        {
            int j = tid >> 2, kc = (tid & 3) * 4;
            float4 f = *(const float4*)(feat + ((size_t)b * T_SEQ + j) * DMODEL + e0 + kc);
            float4 w = *(const float4*)(w2 + e0 + kc);
            Bs[kc + 0][j] = f.x * w.x; Bs[kc + 1][j] = f.y * w.y;
            Bs[kc + 2][j] = f.z * w.z; Bs[kc + 3][j] = f.w * w.w;
        }
        __syncthreads();
#pragma unroll
        for (int k = 0; k < 16; k++) {
            float a[4], bb[8];
            a[0] = As[k][r0]; a[1] = As[k][r0 + 1];
            a[2] = As[k][r0 + 2]; a[3] = As[k][r0 + 3];
            *(float4*)&bb[0] = *(float4*)&Bs[k][j0];
            *(float4*)&bb[4] = *(float4*)&Bs[k][j0 + 4];
#pragma unroll
            for (int i = 0; i < 4; i++)
#pragma unroll
                for (int j = 0; j < 8; j++)
                    acc[i][j] = fmaf(a[i], bb[j], acc[i][j]);
        }
        __syncthreads();
    }
#pragma unroll
    for (int i = 0; i < 4; i++) {
        float* mp = g_M + ((size_t)b * DMODEL + d0 + r0 + i) * WIN + j0;
        *(float4*)mp       = make_float4(acc[i][0], acc[i][1], acc[i][2], acc[i][3]);
        *(float4*)(mp + 4) = make_float4(acc[i][4], acc[i][5], acc[i][6], acc[i][7]);
    }
}

// ---------------------------------------------------------------------------
// k2: P[b] = (feature[b] @ M[b] + biasP) * log2e.  Tile 128x64.
// ---------------------------------------------------------------------------
__global__ __launch_bounds__(256) void p_kernel(const float* __restrict__ feat)
{
    __shared__ float As[16][129];
    __shared__ float Bs[16][68];
    const int b  = blockIdx.y;
    const int t0 = blockIdx.x * 128;
    const int tid = threadIdx.x;
    const int ty = tid >> 3, tx = tid & 7;
    const int r0 = ty * 4, j0 = tx * 8;

    float acc[4][8];
#pragma unroll
    for (int i = 0; i < 4; i++)
#pragma unroll
        for (int j = 0; j < 8; j++) acc[i][j] = 0.f;

    for (int e0 = 0; e0 < DMODEL; e0 += 16) {
#pragma unroll
        for (int l = 0; l < 2; l++) {
            int s = tid + l * 256;
            int r = s >> 2, kc = (s & 3) * 4;
            float4 w = *(const float4*)(feat + ((size_t)b * T_SEQ + t0 + r) * DMODEL + e0 + kc);
            As[kc + 0][r] = w.x; As[kc + 1][r] = w.y;
            As[kc + 2][r] = w.z; As[kc + 3][r] = w.w;
        }
        {
            int k = tid >> 4, j4 = (tid & 15) * 4;
            *(float4*)&Bs[k][j4] =
                *(const float4*)(g_M + ((size_t)b * DMODEL + e0 + k) * WIN + j4);
        }
        __syncthreads();
#pragma unroll
        for (int k = 0; k < 16; k++) {
            float a[4], bb[8];
            a[0] = As[k][r0]; a[1] = As[k][r0 + 1];
            a[2] = As[k][r0 + 2]; a[3] = As[k][r0 + 3];
            *(float4*)&bb[0] = *(float4*)&Bs[k][j0];
            *(float4*)&bb[4] = *(float4*)&Bs[k][j0 + 4];
#pragma unroll
            for (int i = 0; i < 4; i++)
#pragma unroll
                for (int j = 0; j < 8; j++)
                    acc[i][j] = fmaf(a[i], bb[j], acc[i][j]);
        }
        __syncthreads();
    }
    float bj[8];
    *(float4*)&bj[0] = *(const float4*)(g_bP + b * WIN + j0);
    *(float4*)&bj[4] = *(const float4*)(g_bP + b * WIN + j0 + 4);
#pragma unroll
    for (int i = 0; i < 4; i++) {
        float* pp = g_P + ((size_t)b * T_SEQ + t0 + r0 + i) * WIN + j0;
        *(float4*)pp = make_float4((acc[i][0] + bj[0]) * LOG2E, (acc[i][1] + bj[1]) * LOG2E,
                                   (acc[i][2] + bj[2]) * LOG2E, (acc[i][3] + bj[3]) * LOG2E);
        *(float4*)(pp + 4) = make_float4((acc[i][4] + bj[4]) * LOG2E, (acc[i][5] + bj[5]) * LOG2E,
                                         (acc[i][6] + bj[6]) * LOG2E, (acc[i][7] + bj[7]) * LOG2E);
    }
}

// ---------------------------------------------------------------------------
// k3: coefficient-space scan, deferred normalization, vectorized LDS.128 +
// 4 rotating f32x2 accumulators + ex2/rcp approx. 64 threads per batch:
// thread i owns row i (registers) and column i (smem ring, stride 68).
// ---------------------------------------------------------------------------
__global__ __launch_bounds__(64, 1) void scan_kernel()
{
    __shared__ __align__(16) float p_sh[2][WIN];
    __shared__ __align__(16) float e_sh[WIN];
    __shared__ __align__(16) float cnew_sh[WIN];
    __shared__ __align__(16) float Ccs[WIN][68];   // Ccs[j][r] = C[r][j]; 272B rows

    const int b   = blockIdx.x;
    const int tid = threadIdx.x;       // 0..63 = row AND column index

    // C = Identity
    uint64_t CrowP[32];
#pragma unroll
    for (int k = 0; k < 32; k++) {
        float x0 = (2 * k     == tid) ? 1.f : 0.f;
        float x1 = (2 * k + 1 == tid) ? 1.f : 0.f;
        CrowP[k] = ((uint64_t)__float_as_uint(x1) << 32) | __float_as_uint(x0);
    }
    for (int r = 0; r < WIN; r++) Ccs[tid][r] = (r == tid) ? 1.f : 0.f;

    const uint64_t ones = 0x3F8000003F800000ull;  // (1.0f, 1.0f)

    p_sh[0][tid] = g_P[((size_t)b * T_SEQ + WIN) * WIN + tid];
    __syncthreads();

    for (int t = WIN; t < T_SEQ; ++t) {
        const int cur = t & 1, nxt = cur ^ 1;

        // prefetch next p (L2-resident)
        const int tn = (t + 1 < T_SEQ) ? t + 1 : t;
        const float pn = g_P[((size_t)b * T_SEQ + tn) * WIN + tid];

        // phase A: score for own row (16 LDS.128, 32 FFMA2, 4 accumulators)
        const ulonglong2* pc = (const ulonglong2*)&p_sh[cur][0];
        uint64_t a0 = 0, a1 = 0, a2 = 0, a3 = 0;
#pragma unroll
        for (int k = 0; k < 16; k += 2) {
            ulonglong2 pv0 = pc[k];
            ulonglong2 pv1 = pc[k + 1];
            fma2(a0, CrowP[2 * k + 0], pv0.x);
            fma2(a1, CrowP[2 * k + 1], pv0.y);
            fma2(a2, CrowP[2 * k + 2], pv1.x);
            fma2(a3, CrowP[2 * k + 3], pv1.y);
        }
        add2(a0, a1); add2(a2, a3); add2(a0, a2);
        const float e = ex2f(lo2(a0) + hi2(a0));   // P pre-scaled by log2e
        e_sh[tid] = e;
        p_sh[nxt][tid] = pn;
        __syncthreads();

        // phase B: unnormalized update + denominator (32 LDS.128, 64 FFMA2)
        const ulonglong2* ec = (const ulonglong2*)&e_sh[0];
        const ulonglong2* cc = (const ulonglong2*)&Ccs[tid][0];
        uint64_t u0 = 0, u1 = 0, u2 = 0, u3 = 0, d0 = 0, d1 = 0;
#pragma unroll
        for (int k = 0; k < 16; k += 2) {
            ulonglong2 ev0 = ec[k];
            ulonglong2 cv0 = cc[k];
            ulonglong2 ev1 = ec[k + 1];
            ulonglong2 cv1 = cc[k + 1];
            fma2(u0, ev0.x, cv0.x);
            fma2(u1, ev0.y, cv0.y);
            fma2(u2, ev1.x, cv1.x);
            fma2(u3, ev1.y, cv1.y);
            fma2(d0, ev0.x, ones);
            fma2(d1, ev0.y, ones);
            fma2(d0, ev1.x, ones);
            fma2(d1, ev1.y, ones);
        }
        add2(u0, u1); add2(u2, u3); add2(u0, u2);
        add2(d0, d1);
        const float inv = rcpf(lo2(d0) + hi2(d0) + 1.f);
        const float c   = (lo2(u0) + hi2(u0)) * inv;

        g_C[((size_t)b * T_SEQ + t) * WIN + tid] = c;
        cnew_sh[tid] = c;
        const int slot = t & (WIN - 1);
        Ccs[tid][slot] = c;            // own column, thread-private
        __syncthreads();

        // ring: thread 'slot' replaces its register row with c_new
        if (tid == slot) {
            const ulonglong2* cn = (const ulonglong2*)&cnew_sh[0];
#pragma unroll
            for (int k = 0; k < 16; k++) {
                ulonglong2 v = cn[k];
                CrowP[2 * k]     = v.x;
                CrowP[2 * k + 1] = v.y;
            }
        }
    }
}

// ---------------------------------------------------------------------------
// k4: V[b] = C[b] (2048x64) @ F[b] (64x1024) -> d_out for t>=64.
// ---------------------------------------------------------------------------
__global__ __launch_bounds__(256) void v_kernel(
    const float* __restrict__ feat, float* __restrict__ out)
{
    __shared__ float Cst[64][68];
    __shared__ float Fs[64][64];
    const int b  = blockIdx.z;
    const int t0 = blockIdx.x * 64;
    const int d0 = blockIdx.y * 64;
    const int tid = threadIdx.x;
    const int ty = tid >> 4, tx = tid & 15;
    const int r0 = ty * 4, c0 = tx * 4;

#pragma unroll
    for (int l = 0; l < 4; l++) {
        int s = tid + l * 256;
        int r = s >> 4, j4 = (s & 15) * 4;
        float4 c = *(const float4*)(g_C + ((size_t)b * T_SEQ + t0 + r) * WIN + j4);
        Cst[j4 + 0][r] = c.x; Cst[j4 + 1][r] = c.y;
        Cst[j4 + 2][r] = c.z; Cst[j4 + 3][r] = c.w;
    }
#pragma unroll
    for (int l = 0; l < 4; l++) {
        int s = tid + l * 256;
        int j = s >> 4, c4 = (s & 15) * 4;
        *(float4*)&Fs[j][c4] =
            *(const float4*)(feat + ((size_t)b * T_SEQ + j) * DMODEL + d0 + c4);
    }
    __syncthreads();

    float acc[4][4];
#pragma unroll
    for (int i = 0; i < 4; i++)
#pragma unroll
        for (int j = 0; j < 4; j++) acc[i][j] = 0.f;

#pragma unroll 8
    for (int k = 0; k < 64; k++) {
        float a[4], bb[4];
        a[0] = Cst[k][r0]; a[1] = Cst[k][r0 + 1];
        a[2] = Cst[k][r0 + 2]; a[3] = Cst[k][r0 + 3];
        *(float4*)&bb[0] = *(float4*)&Fs[k][c0];
#pragma unroll
        for (int i = 0; i < 4; i++)
#pragma unroll
            for (int j = 0; j < 4; j++)
                acc[i][j] = fmaf(a[i], bb[j], acc[i][j]);
    }

#pragma unroll
    for (int i = 0; i < 4; i++) {
        int t = t0 + r0 + i;
        if (t >= WIN) {
            *(float4*)(out + ((size_t)b * T_SEQ + t) * DMODEL + d0 + c0) =
                make_float4(acc[i][0], acc[i][1], acc[i][2], acc[i][3]);
        }
    }
}

// ---------------------------------------------------------------------------
// k5: epilogue y = tanh(v)*f + f, LayerNorm.
// ---------------------------------------------------------------------------
__global__ __launch_bounds__(256) void ln_kernel(
    const float* __restrict__ feature, const float* __restrict__ g,
    const float* __restrict__ bt, float* __restrict__ out)
{
    const int row = blockIdx.x;
    const int t = row & (T_SEQ - 1);
    const float* fp = feature + (size_t)row * DMODEL;
    float* op = out + (size_t)row * DMODEL;
    const float* vp = (t < WIN) ? fp : op;
    const int tid = threadIdx.x;
    const int lane = tid & 31, warp = tid >> 5;

    float4 f = *(const float4*)(fp + tid * 4);
    float4 v = *(const float4*)(vp + tid * 4);
    float y0 = tanhf(v.x) * f.x + f.x;
    float y1 = tanhf(v.y) * f.y + f.y;
    float y2 = tanhf(v.z) * f.z + f.z;
    float y3 = tanhf(v.w) * f.w + f.w;

    float s  = y0 + y1 + y2 + y3;
    float ss = y0 * y0 + y1 * y1 + y2 * y2 + y3 * y3;
#pragma unroll
    for (int o = 16; o > 0; o >>= 1) {
        s  += __shfl_xor_sync(0xffffffffu, s, o);
        ss += __shfl_xor_sync(0xffffffffu, ss, o);
    }
    __shared__ float red[8][2];
    if (lane == 0) { red[warp][0] = s; red[warp][1] = ss; }
    __syncthreads();
    if (warp == 0) {
        float a = (lane < 8) ? red[lane][0] : 0.f;
        float c = (lane < 8) ? red[lane][1] : 0.f;
#pragma unroll
        for (int o = 4; o > 0; o >>= 1) {
            a += __shfl_xor_sync(0xffffffffu, a, o);
            c += __shfl_xor_sync(0xffffffffu, c, o);
        }
        if (lane == 0) { red[0][0] = a; red[0][1] = c; }
    }
    __syncthreads();
    const float mu   = red[0][0] * (1.f / DMODEL);
    const float var  = red[0][1] * (1.f / DMODEL) - mu * mu;
    const float rstd = rsqrtf(var + 1e-5f);

    float4 gg = *(const float4*)(g + tid * 4);
    float4 bb = *(const float4*)(bt + tid * 4);
    float4 o;
    o.x = (y0 - mu) * rstd * gg.x + bb.x;
    o.y = (y1 - mu) * rstd * gg.y + bb.y;
    o.z = (y2 - mu) * rstd * gg.z + bb.z;
    o.w = (y3 - mu) * rstd * gg.w + bb.w;
    *(float4*)(op + tid * 4) = o;
}

// ---------------------------------------------------------------------------
extern "C" void kernel_launch(void* const* d_in, const int* in_sizes, int n_in,
                              void* d_out, int out_size)
{
    const float* feature = (const float*)d_in[0];
    const float* wq_w    = (const float*)d_in[1];
    const float* wq_b    = (const float*)d_in[2];
    const float* w2_w    = (const float*)d_in[3];
    // d_in[4] = w2_b: cancels by softmax shift-invariance
    const float* ln_g    = (const float*)d_in[5];
    const float* ln_b    = (const float*)d_in[6];
    float* out = (float*)d_out;

    bias_p_kernel<<<BATCH, 256>>>(feature, wq_b, w2_w);
    m_kernel<<<dim3(8, BATCH), 256>>>(wq_w, w2_w, feature);
    p_kernel<<<dim3(16, BATCH), 256>>>(feature);
    scan_kernel<<<BATCH, 64>>>();
    v_kernel<<<dim3(32, 16, BATCH), 256>>>(feature, out);
    ln_kernel<<<BATCH * T_SEQ, 256>>>(feature, ln_g, ln_b, out);
}

// round 9
// speedup vs baseline: 1.3211x; 1.3211x over previous
#include <cuda_runtime.h>
#include <cstdint>

#define T_SEQ  2048
#define BATCH  8
#define DMODEL 1024
#define WIN    64
#define LOG2E  1.4426950408889634f

// Scratch (≈10 MB total)
__device__ float g_M[(size_t)BATCH * DMODEL * WIN];   // M[b][d][j]
__device__ float g_P[(size_t)BATCH * T_SEQ * WIN];    // p_t[j]*log2e per batch
__device__ float g_C[(size_t)BATCH * T_SEQ * WIN];    // coefficients of v_t
__device__ float g_bP[BATCH * WIN];                   // bias term of p

// packed f32x2 helpers
__device__ __forceinline__ void fma2(uint64_t& acc, uint64_t a, uint64_t b) {
    asm("fma.rn.f32x2 %0, %1, %2, %0;" : "+l"(acc) : "l"(a), "l"(b));
}
__device__ __forceinline__ void add2(uint64_t& a, uint64_t b) {
    asm("add.rn.f32x2 %0, %0, %1;" : "+l"(a) : "l"(b));
}
__device__ __forceinline__ float lo2(uint64_t v) {
    return __uint_as_float((uint32_t)v);
}
__device__ __forceinline__ float hi2(uint64_t v) {
    return __uint_as_float((uint32_t)(v >> 32));
}
__device__ __forceinline__ float ex2f(float x) {
    float r; asm("ex2.approx.ftz.f32 %0, %1;" : "=f"(r) : "f"(x)); return r;
}
__device__ __forceinline__ float rcpf(float x) {
    float r; asm("rcp.approx.ftz.f32 %0, %1;" : "=f"(r) : "f"(x)); return r;
}

// ---------------------------------------------------------------------------
// biasP[b][j] = sum_e wq_b[e] * w2[e] * F[b][j][e]
// ---------------------------------------------------------------------------
__global__ __launch_bounds__(256) void bias_p_kernel(
    const float* __restrict__ feat, const float* __restrict__ wqb,
    const float* __restrict__ w2)
{
    const int b = blockIdx.x;
    const int j = threadIdx.x >> 2;
    const int q = threadIdx.x & 3;
    const float* fp = feat + ((size_t)b * T_SEQ + j) * DMODEL + q * 256;
    float s = 0.f;
#pragma unroll 4
    for (int e = 0; e < 256; e += 4) {
        float4 f  = *(const float4*)(fp + e);
        float4 wb = *(const float4*)(wqb + q * 256 + e);
        float4 ww = *(const float4*)(w2 + q * 256 + e);
        s += f.x * wb.x * ww.x + f.y * wb.y * ww.y +
             f.z * wb.z * ww.z + f.w * wb.w * ww.w;
    }
    s += __shfl_xor_sync(0xffffffffu, s, 1);
    s += __shfl_xor_sync(0xffffffffu, s, 2);
    if (q == 0) g_bP[b * WIN + j] = s;
}

// ---------------------------------------------------------------------------
// k1: M[b] = wq @ (F[b,:64]*w2)^T.  Tile 128x64, K=1024.
// ---------------------------------------------------------------------------
__global__ __launch_bounds__(256) void m_kernel(
    const float* __restrict__ wq, const float* __restrict__ w2,
    const float* __restrict__ feat)
{
    __shared__ float As[16][129];
    __shared__ float Bs[16][68];
    const int b  = blockIdx.y;
    const int d0 = blockIdx.x * 128;
    const int tid = threadIdx.x;
    const int ty = tid >> 3, tx = tid & 7;
    const int r0 = ty * 4, j0 = tx * 8;

    float acc[4][8];
#pragma unroll
    for (int i = 0; i < 4; i++)
#pragma unroll
        for (int j = 0; j < 8; j++) acc[i][j] = 0.f;

    for (int e0 = 0; e0 < DMODEL; e0 += 16) {
#pragma unroll
        for (int l = 0; l < 2; l++) {
            int s = tid + l * 256;
            int r = s >> 2, kc = (s & 3) * 4;
            float4 w = *(const float4*)(wq + (size_t)(d0 + r) * DMODEL + e0 + kc);
            As[kc + 0][r] = w.x; As[kc + 1][r] = w.y;
            As[kc + 2][r] = w.z; As[kc + 3][r] = w.w;
        }
        {
            int j = tid >> 2, kc = (tid & 3) * 4;
            float4 f = *(const float4*)(feat + ((size_t)b * T_SEQ + j) * DMODEL + e0 + kc);
            float4 w = *(const float4*)(w2 + e0 + kc);
            Bs[kc + 0][j] = f.x * w.x; Bs[kc + 1][j] = f.y * w.y;
            Bs[kc + 2][j] = f.z * w.z; Bs[kc + 3][j] = f.w * w.w;
        }
        __syncthreads();
#pragma unroll
        for (int k = 0; k < 16; k++) {
            float a[4], bb[8];
            a[0] = As[k][r0]; a[1] = As[k][r0 + 1];
            a[2] = As[k][r0 + 2]; a[3] = As[k][r0 + 3];
            *(float4*)&bb[0] = *(float4*)&Bs[k][j0];
            *(float4*)&bb[4] = *(float4*)&Bs[k][j0 + 4];
#pragma unroll
            for (int i = 0; i < 4; i++)
#pragma unroll
                for (int j = 0; j < 8; j++)
                    acc[i][j] = fmaf(a[i], bb[j], acc[i][j]);
        }
        __syncthreads();
    }
#pragma unroll
    for (int i = 0; i < 4; i++) {
        float* mp = g_M + ((size_t)b * DMODEL + d0 + r0 + i) * WIN + j0;
        *(float4*)mp       = make_float4(acc[i][0], acc[i][1], acc[i][2], acc[i][3]);
        *(float4*)(mp + 4) = make_float4(acc[i][4], acc[i][5], acc[i][6], acc[i][7]);
    }
}

// ---------------------------------------------------------------------------
// k2: P[b] = (feature[b] @ M[b] + biasP) * log2e.  Tile 128x64.
// ---------------------------------------------------------------------------
__global__ __launch_bounds__(256) void p_kernel(const float* __restrict__ feat)
{
    __shared__ float As[16][129];
    __shared__ float Bs[16][68];
    const int b  = blockIdx.y;
    const int t0 = blockIdx.x * 128;
    const int tid = threadIdx.x;
    const int ty = tid >> 3, tx = tid & 7;
    const int r0 = ty * 4, j0 = tx * 8;

    float acc[4][8];
#pragma unroll
    for (int i = 0; i < 4; i++)
#pragma unroll
        for (int j = 0; j < 8; j++) acc[i][j] = 0.f;

    for (int e0 = 0; e0 < DMODEL; e0 += 16) {
#pragma unroll
        for (int l = 0; l < 2; l++) {
            int s = tid + l * 256;
            int r = s >> 2, kc = (s & 3) * 4;
            float4 w = *(const float4*)(feat + ((size_t)b * T_SEQ + t0 + r) * DMODEL + e0 + kc);
            As[kc + 0][r] = w.x; As[kc + 1][r] = w.y;
            As[kc + 2][r] = w.z; As[kc + 3][r] = w.w;
        }
        {
            int k = tid >> 4, j4 = (tid & 15) * 4;
            *(float4*)&Bs[k][j4] =
                *(const float4*)(g_M + ((size_t)b * DMODEL + e0 + k) * WIN + j4);
        }
        __syncthreads();
#pragma unroll
        for (int k = 0; k < 16; k++) {
            float a[4], bb[8];
            a[0] = As[k][r0]; a[1] = As[k][r0 + 1];
            a[2] = As[k][r0 + 2]; a[3] = As[k][r0 + 3];
            *(float4*)&bb[0] = *(float4*)&Bs[k][j0];
            *(float4*)&bb[4] = *(float4*)&Bs[k][j0 + 4];
#pragma unroll
            for (int i = 0; i < 4; i++)
#pragma unroll
                for (int j = 0; j < 8; j++)
                    acc[i][j] = fmaf(a[i], bb[j], acc[i][j]);
        }
        __syncthreads();
    }
    float bj[8];
    *(float4*)&bj[0] = *(const float4*)(g_bP + b * WIN + j0);
    *(float4*)&bj[4] = *(const float4*)(g_bP + b * WIN + j0 + 4);
#pragma unroll
    for (int i = 0; i < 4; i++) {
        float* pp = g_P + ((size_t)b * T_SEQ + t0 + r0 + i) * WIN + j0;
        *(float4*)pp = make_float4((acc[i][0] + bj[0]) * LOG2E, (acc[i][1] + bj[1]) * LOG2E,
                                   (acc[i][2] + bj[2]) * LOG2E, (acc[i][3] + bj[3]) * LOG2E);
        *(float4*)(pp + 4) = make_float4((acc[i][4] + bj[4]) * LOG2E, (acc[i][5] + bj[5]) * LOG2E,
                                         (acc[i][6] + bj[6]) * LOG2E, (acc[i][7] + bj[7]) * LOG2E);
    }
}

// ---------------------------------------------------------------------------
// k3: coefficient-space scan — 128 threads, ONE barrier per step.
// Thread (i,h): i=row/col index, h=half. lane = (i&15)+16h so (i,0)/(i,1)
// share a warp and combine halves with shfl_xor(16).
// Step t carries scores vs p_{t+1} (x_r = e_r*sig'_r); next step rebuilds the
// replaced row's exp as e_hat = ex2(inv_prev * sum(x)) and patches the one
// stale e in the u/d sums via dE = e_hat - e_stale.
// Cross-step smem double-buffered by parity; Ccs columns are single-owner.
// ---------------------------------------------------------------------------
__global__ __launch_bounds__(128, 1) void scan_kernel()
{
    __shared__ __align__(16) float p_buf[2][WIN];
    __shared__ __align__(16) float e_buf[2][WIN];
    __shared__ __align__(16) float x_buf[2][WIN];
    __shared__ __align__(16) float cnew_buf[2][WIN];
    __shared__ __align__(16) float Ccs[WIN][68];   // Ccs[i][r] = C[r][i]

    const int b    = blockIdx.x;
    const int tid  = threadIdx.x;
    const int warp = tid >> 5;
    const int lane = tid & 31;
    const int h    = lane >> 4;                 // half 0/1
    const int i    = (lane & 15) | (warp << 4); // row & column index 0..63
    const int rb   = h << 5;                    // own half start (j and r)

    // C = Identity. CrowP[k] = (C[i][rb+2k], C[i][rb+2k+1])
    uint64_t CrowP[16];
#pragma unroll
    for (int k = 0; k < 16; k++) {
        int j0 = rb + 2 * k;
        float x0 = (j0     == i) ? 1.f : 0.f;
        float x1 = (j0 + 1 == i) ? 1.f : 0.f;
        CrowP[k] = ((uint64_t)__float_as_uint(x1) << 32) | __float_as_uint(x0);
    }
    for (int r = rb; r < rb + 32; r++) Ccs[i][r] = (r == i) ? 1.f : 0.f;

    // Bootstrap: scores vs p_64 are just p_64 (C = I). Seed parity-1 buffers
    // so iteration t=64 sees a consistent "previous step" with dE == 0.
    const float p64 = g_P[((size_t)b * T_SEQ + WIN) * WIN + i];
    float e_own = ex2f(p64);
    float inv_prev = 1.f;
    if (h == 0) {
        e_buf[1][i]    = e_own;
        x_buf[1][i]    = (i == 63) ? p64 : 0.f;   // => e_hat == e_buf[63]
        cnew_buf[1][i] = (i == 63) ? 1.f : 0.f;   // row 63 "reload" is identity
        p_buf[1][i]    = g_P[((size_t)b * T_SEQ + WIN + 1) * WIN + i];
    }
    __syncthreads();

    for (int t = WIN; t < T_SEQ; ++t) {
        const int cur = t & 1, prev = cur ^ 1;
        const int slotp = (t - 1) & (WIN - 1);
        const int slot  = t & (WIN - 1);

        // prefetch p_{t+2} (consumed at end of this iter into p_buf[cur])
        float pn = 0.f;
        if (h == 0) {
            int tn = (t + 2 < T_SEQ) ? t + 2 : T_SEQ - 1;
            pn = g_P[((size_t)b * T_SEQ + tn) * WIN + i];
        }

        // the row replaced last step reloads its register half
        if (i == slotp) {
            const ulonglong2* cn = (const ulonglong2*)&cnew_buf[prev][rb];
#pragma unroll
            for (int k = 0; k < 8; k++) {
                ulonglong2 v = cn[k];
                CrowP[2 * k]     = v.x;
                CrowP[2 * k + 1] = v.y;
            }
        }

        const float e_stale = e_buf[prev][slotp];
        const float ccs_sp  = Ccs[i][slotp];      // = c_{t-1}[i]

        // fused: S = sum x (own half), d = sum e, u = sum e*Ccs[i][.]
        const ulonglong2* ep = (const ulonglong2*)&e_buf[prev][rb];
        const ulonglong2* xp = (const ulonglong2*)&x_buf[prev][rb];
        const ulonglong2* cc = (const ulonglong2*)&Ccs[i][rb];
        uint64_t s0 = 0, s1 = 0, d0 = 0, d1 = 0, u0 = 0, u1 = 0;
#pragma unroll
        for (int k = 0; k < 8; k++) {
            ulonglong2 e2 = ep[k];
            ulonglong2 x2 = xp[k];
            ulonglong2 c2 = cc[k];
            add2(s0, x2.x); add2(s1, x2.y);
            add2(d0, e2.x); add2(d1, e2.y);
            fma2(u0, e2.x, c2.x);
            fma2(u1, e2.y, c2.y);
        }
        add2(s0, s1); add2(d0, d1); add2(u0, u1);
        float S = lo2(s0) + hi2(s0);
        float d = lo2(d0) + hi2(d0);
        float u = lo2(u0) + hi2(u0);
        S += __shfl_xor_sync(0xffffffffu, S, 16);
        d += __shfl_xor_sync(0xffffffffu, d, 16);
        u += __shfl_xor_sync(0xffffffffu, u, 16);

        const float e_hat = ex2f(inv_prev * S);   // exp of replaced row vs p_t
        const float dE    = e_hat - e_stale;
        const float inv   = rcpf(d + dE + 1.f);   // +1 = zero-row of softmax
        const float c_i   = (u + dE * ccs_sp) * inv;
        inv_prev = inv;

        // scores of current rows vs p_{t+1} (independent chain)
        const ulonglong2* pp = (const ulonglong2*)&p_buf[prev][rb];
        uint64_t g0 = 0, g1 = 0;
#pragma unroll
        for (int k = 0; k < 8; k++) {
            ulonglong2 p2 = pp[k];
            fma2(g0, CrowP[2 * k],     p2.x);
            fma2(g1, CrowP[2 * k + 1], p2.y);
        }
        add2(g0, g1);
        float sig = lo2(g0) + hi2(g0);
        sig += __shfl_xor_sync(0xffffffffu, sig, 16);
        const float e_new = ex2f(sig);
        const float e_use = (i == slotp) ? e_hat : e_own;  // this row's e at step t
        const float x_new = e_use * sig;
        e_own = e_new;

        // writes (column i is pair-private; rest is parity-buffered)
        if ((slot >> 5) == h) Ccs[i][slot] = c_i;
        if (h == 0) {
            e_buf[cur][i]    = e_new;
            x_buf[cur][i]    = x_new;
            cnew_buf[cur][i] = c_i;
            p_buf[cur][i]    = pn;
            g_C[((size_t)b * T_SEQ + t) * WIN + i] = c_i;
        }
        __syncthreads();
    }
}

// ---------------------------------------------------------------------------
// k4: V[b] = C[b] (2048x64) @ F[b] (64x1024) -> d_out for t>=64.
// ---------------------------------------------------------------------------
__global__ __launch_bounds__(256) void v_kernel(
    const float* __restrict__ feat, float* __restrict__ out)
{
    __shared__ float Cst[64][68];
    __shared__ float Fs[64][64];
    const int b  = blockIdx.z;
    const int t0 = blockIdx.x * 64;
    const int d0 = blockIdx.y * 64;
    const int tid = threadIdx.x;
    const int ty = tid >> 4, tx = tid & 15;
    const int r0 = ty * 4, c0 = tx * 4;

#pragma unroll
    for (int l = 0; l < 4; l++) {
        int s = tid + l * 256;
        int r = s >> 4, j4 = (s & 15) * 4;
        float4 c = *(const float4*)(g_C + ((size_t)b * T_SEQ + t0 + r) * WIN + j4);
        Cst[j4 + 0][r] = c.x; Cst[j4 + 1][r] = c.y;
        Cst[j4 + 2][r] = c.z; Cst[j4 + 3][r] = c.w;
    }
#pragma unroll
    for (int l = 0; l < 4; l++) {
        int s = tid + l * 256;
        int j = s >> 4, c4 = (s & 15) * 4;
        *(float4*)&Fs[j][c4] =
            *(const float4*)(feat + ((size_t)b * T_SEQ + j) * DMODEL + d0 + c4);
    }
    __syncthreads();

    float acc[4][4];
#pragma unroll
    for (int i = 0; i < 4; i++)
#pragma unroll
        for (int j = 0; j < 4; j++) acc[i][j] = 0.f;

#pragma unroll 8
    for (int k = 0; k < 64; k++) {
        float a[4], bb[4];
        a[0] = Cst[k][r0]; a[1] = Cst[k][r0 + 1];
        a[2] = Cst[k][r0 + 2]; a[3] = Cst[k][r0 + 3];
        *(float4*)&bb[0] = *(float4*)&Fs[k][c0];
#pragma unroll
        for (int i = 0; i < 4; i++)
#pragma unroll
            for (int j = 0; j < 4; j++)
                acc[i][j] = fmaf(a[i], bb[j], acc[i][j]);
    }

#pragma unroll
    for (int i = 0; i < 4; i++) {
        int t = t0 + r0 + i;
        if (t >= WIN) {
            *(float4*)(out + ((size_t)b * T_SEQ + t) * DMODEL + d0 + c0) =
                make_float4(acc[i][0], acc[i][1], acc[i][2], acc[i][3]);
        }
    }
}

// ---------------------------------------------------------------------------
// k5: epilogue y = tanh(v)*f + f, LayerNorm.
// ---------------------------------------------------------------------------
__global__ __launch_bounds__(256) void ln_kernel(
    const float* __restrict__ feature, const float* __restrict__ g,
    const float* __restrict__ bt, float* __restrict__ out)
{
    const int row = blockIdx.x;
    const int t = row & (T_SEQ - 1);
    const float* fp = feature + (size_t)row * DMODEL;
    float* op = out + (size_t)row * DMODEL;
    const float* vp = (t < WIN) ? fp : op;
    const int tid = threadIdx.x;
    const int lane = tid & 31, warp = tid >> 5;

    float4 f = *(const float4*)(fp + tid * 4);
    float4 v = *(const float4*)(vp + tid * 4);
    float y0 = tanhf(v.x) * f.x + f.x;
    float y1 = tanhf(v.y) * f.y + f.y;
    float y2 = tanhf(v.z) * f.z + f.z;
    float y3 = tanhf(v.w) * f.w + f.w;

    float s  = y0 + y1 + y2 + y3;
    float ss = y0 * y0 + y1 * y1 + y2 * y2 + y3 * y3;
#pragma unroll
    for (int o = 16; o > 0; o >>= 1) {
        s  += __shfl_xor_sync(0xffffffffu, s, o);
        ss += __shfl_xor_sync(0xffffffffu, ss, o);
    }
    __shared__ float red[8][2];
    if (lane == 0) { red[warp][0] = s; red[warp][1] = ss; }
    __syncthreads();
    if (warp == 0) {
        float a = (lane < 8) ? red[lane][0] : 0.f;
        float c = (lane < 8) ? red[lane][1] : 0.f;
#pragma unroll
        for (int o = 4; o > 0; o >>= 1) {
            a += __shfl_xor_sync(0xffffffffu, a, o);
            c += __shfl_xor_sync(0xffffffffu, c, o);
        }
        if (lane == 0) { red[0][0] = a; red[0][1] = c; }
    }
    __syncthreads();
    const float mu   = red[0][0] * (1.f / DMODEL);
    const float var  = red[0][1] * (1.f / DMODEL) - mu * mu;
    const float rstd = rsqrtf(var + 1e-5f);

    float4 gg = *(const float4*)(g + tid * 4);
    float4 bb = *(const float4*)(bt + tid * 4);
    float4 o;
    o.x = (y0 - mu) * rstd * gg.x + bb.x;
    o.y = (y1 - mu) * rstd * gg.y + bb.y;
    o.z = (y2 - mu) * rstd * gg.z + bb.z;
    o.w = (y3 - mu) * rstd * gg.w + bb.w;
    *(float4*)(op + tid * 4) = o;
}

// ---------------------------------------------------------------------------
extern "C" void kernel_launch(void* const* d_in, const int* in_sizes, int n_in,
                              void* d_out, int out_size)
{
    const float* feature = (const float*)d_in[0];
    const float* wq_w    = (const float*)d_in[1];
    const float* wq_b    = (const float*)d_in[2];
    const float* w2_w    = (const float*)d_in[3];
    // d_in[4] = w2_b: cancels by softmax shift-invariance
    const float* ln_g    = (const float*)d_in[5];
    const float* ln_b    = (const float*)d_in[6];
    float* out = (float*)d_out;

    bias_p_kernel<<<BATCH, 256>>>(feature, wq_b, w2_w);
    m_kernel<<<dim3(8, BATCH), 256>>>(wq_w, w2_w, feature);
    p_kernel<<<dim3(16, BATCH), 256>>>(feature);
    scan_kernel<<<BATCH, 128>>>();
    v_kernel<<<dim3(32, 16, BATCH), 256>>>(feature, out);
    ln_kernel<<<BATCH * T_SEQ, 256>>>(feature, ln_g, ln_b, out);
}

// round 11
// speedup vs baseline: 1.4321x; 1.0840x over previous
#include <cuda_runtime.h>
#include <cstdint>

#define T_SEQ  2048
#define BATCH  8
#define DMODEL 1024
#define WIN    64
#define LOG2E  1.4426950408889634f

// Scratch (≈10 MB total)
__device__ float g_M[(size_t)BATCH * DMODEL * WIN];   // M[b][d][j]
__device__ float g_P[(size_t)BATCH * T_SEQ * WIN];    // p_t[j]*log2e per batch
__device__ float g_C[(size_t)BATCH * T_SEQ * WIN];    // coefficients of v_t
__device__ float g_bP[BATCH * WIN];                   // bias term of p

// packed f32x2 helpers
__device__ __forceinline__ void fma2(uint64_t& acc, uint64_t a, uint64_t b) {
    asm("fma.rn.f32x2 %0, %1, %2, %0;" : "+l"(acc) : "l"(a), "l"(b));
}
__device__ __forceinline__ void add2(uint64_t& a, uint64_t b) {
    asm("add.rn.f32x2 %0, %0, %1;" : "+l"(a) : "l"(b));
}
__device__ __forceinline__ float lo2(uint64_t v) {
    return __uint_as_float((uint32_t)v);
}
__device__ __forceinline__ float hi2(uint64_t v) {
    return __uint_as_float((uint32_t)(v >> 32));
}
__device__ __forceinline__ float ex2f(float x) {
    float r; asm("ex2.approx.ftz.f32 %0, %1;" : "=f"(r) : "f"(x)); return r;
}
__device__ __forceinline__ float rcpf(float x) {
    float r; asm("rcp.approx.ftz.f32 %0, %1;" : "=f"(r) : "f"(x)); return r;
}

// ---------------------------------------------------------------------------
// biasP[b][j] = sum_e wq_b[e] * w2[e] * F[b][j][e]
// ---------------------------------------------------------------------------
__global__ __launch_bounds__(256) void bias_p_kernel(
    const float* __restrict__ feat, const float* __restrict__ wqb,
    const float* __restrict__ w2)
{
    const int b = blockIdx.x;
    const int j = threadIdx.x >> 2;
    const int q = threadIdx.x & 3;
    const float* fp = feat + ((size_t)b * T_SEQ + j) * DMODEL + q * 256;
    float s = 0.f;
#pragma unroll 4
    for (int e = 0; e < 256; e += 4) {
        float4 f  = *(const float4*)(fp + e);
        float4 wb = *(const float4*)(wqb + q * 256 + e);
        float4 ww = *(const float4*)(w2 + q * 256 + e);
        s += f.x * wb.x * ww.x + f.y * wb.y * ww.y +
             f.z * wb.z * ww.z + f.w * wb.w * ww.w;
    }
    s += __shfl_xor_sync(0xffffffffu, s, 1);
    s += __shfl_xor_sync(0xffffffffu, s, 2);
    if (q == 0) g_bP[b * WIN + j] = s;
}

// ---------------------------------------------------------------------------
// k1: M[b] = wq @ (F[b,:64]*w2)^T.  Tile 128x64, K=1024.
// ---------------------------------------------------------------------------
__global__ __launch_bounds__(256) void m_kernel(
    const float* __restrict__ wq, const float* __restrict__ w2,
    const float* __restrict__ feat)
{
    __shared__ float As[16][129];
    __shared__ float Bs[16][68];
    const int b  = blockIdx.y;
    const int d0 = blockIdx.x * 128;
    const int tid = threadIdx.x;
    const int ty = tid >> 3, tx = tid & 7;
    const int r0 = ty * 4, j0 = tx * 8;

    float acc[4][8];
#pragma unroll
    for (int i = 0; i < 4; i++)
#pragma unroll
        for (int j = 0; j < 8; j++) acc[i][j] = 0.f;

    for (int e0 = 0; e0 < DMODEL; e0 += 16) {
#pragma unroll
        for (int l = 0; l < 2; l++) {
            int s = tid + l * 256;
            int r = s >> 2, kc = (s & 3) * 4;
            float4 w = *(const float4*)(wq + (size_t)(d0 + r) * DMODEL + e0 + kc);
            As[kc + 0][r] = w.x; As[kc + 1][r] = w.y;
            As[kc + 2][r] = w.z; As[kc + 3][r] = w.w;
        }
        {
            int j = tid >> 2, kc = (tid & 3) * 4;
            float4 f = *(const float4*)(feat + ((size_t)b * T_SEQ + j) * DMODEL + e0 + kc);
            float4 w = *(const float4*)(w2 + e0 + kc);
            Bs[kc + 0][j] = f.x * w.x; Bs[kc + 1][j] = f.y * w.y;
            Bs[kc + 2][j] = f.z * w.z; Bs[kc + 3][j] = f.w * w.w;
        }
        __syncthreads();
#pragma unroll
        for (int k = 0; k < 16; k++) {
            float a[4], bb[8];
            a[0] = As[k][r0]; a[1] = As[k][r0 + 1];
            a[2] = As[k][r0 + 2]; a[3] = As[k][r0 + 3];
            *(float4*)&bb[0] = *(float4*)&Bs[k][j0];
            *(float4*)&bb[4] = *(float4*)&Bs[k][j0 + 4];
#pragma unroll
            for (int i = 0; i < 4; i++)
#pragma unroll
                for (int j = 0; j < 8; j++)
                    acc[i][j] = fmaf(a[i], bb[j], acc[i][j]);
        }
        __syncthreads();
    }
#pragma unroll
    for (int i = 0; i < 4; i++) {
        float* mp = g_M + ((size_t)b * DMODEL + d0 + r0 + i) * WIN + j0;
        *(float4*)mp       = make_float4(acc[i][0], acc[i][1], acc[i][2], acc[i][3]);
        *(float4*)(mp + 4) = make_float4(acc[i][4], acc[i][5], acc[i][6], acc[i][7]);
    }
}

// ---------------------------------------------------------------------------
// k2: P[b] = (feature[b] @ M[b] + biasP) * log2e.  Tile 128x64.
// ---------------------------------------------------------------------------
__global__ __launch_bounds__(256) void p_kernel(const float* __restrict__ feat)
{
    __shared__ float As[16][129];
    __shared__ float Bs[16][68];
    const int b  = blockIdx.y;
    const int t0 = blockIdx.x * 128;
    const int tid = threadIdx.x;
    const int ty = tid >> 3, tx = tid & 7;
    const int r0 = ty * 4, j0 = tx * 8;

    float acc[4][8];
#pragma unroll
    for (int i = 0; i < 4; i++)
#pragma unroll
        for (int j = 0; j < 8; j++) acc[i][j] = 0.f;

    for (int e0 = 0; e0 < DMODEL; e0 += 16) {
#pragma unroll
        for (int l = 0; l < 2; l++) {
            int s = tid + l * 256;
            int r = s >> 2, kc = (s & 3) * 4;
            float4 w = *(const float4*)(feat + ((size_t)b * T_SEQ + t0 + r) * DMODEL + e0 + kc);
            As[kc + 0][r] = w.x; As[kc + 1][r] = w.y;
            As[kc + 2][r] = w.z; As[kc + 3][r] = w.w;
        }
        {
            int k = tid >> 4, j4 = (tid & 15) * 4;
            *(float4*)&Bs[k][j4] =
                *(const float4*)(g_M + ((size_t)b * DMODEL + e0 + k) * WIN + j4);
        }
        __syncthreads();
#pragma unroll
        for (int k = 0; k < 16; k++) {
            float a[4], bb[8];
            a[0] = As[k][r0]; a[1] = As[k][r0 + 1];
            a[2] = As[k][r0 + 2]; a[3] = As[k][r0 + 3];
            *(float4*)&bb[0] = *(float4*)&Bs[k][j0];
            *(float4*)&bb[4] = *(float4*)&Bs[k][j0 + 4];
#pragma unroll
            for (int i = 0; i < 4; i++)
#pragma unroll
                for (int j = 0; j < 8; j++)
                    acc[i][j] = fmaf(a[i], bb[j], acc[i][j]);
        }
        __syncthreads();
    }
    float bj[8];
    *(float4*)&bj[0] = *(const float4*)(g_bP + b * WIN + j0);
    *(float4*)&bj[4] = *(const float4*)(g_bP + b * WIN + j0 + 4);
#pragma unroll
    for (int i = 0; i < 4; i++) {
        float* pp = g_P + ((size_t)b * T_SEQ + t0 + r0 + i) * WIN + j0;
        *(float4*)pp = make_float4((acc[i][0] + bj[0]) * LOG2E, (acc[i][1] + bj[1]) * LOG2E,
                                   (acc[i][2] + bj[2]) * LOG2E, (acc[i][3] + bj[3]) * LOG2E);
        *(float4*)(pp + 4) = make_float4((acc[i][4] + bj[4]) * LOG2E, (acc[i][5] + bj[5]) * LOG2E,
                                         (acc[i][6] + bj[6]) * LOG2E, (acc[i][7] + bj[7]) * LOG2E);
    }
}

// ---------------------------------------------------------------------------
// k3: coefficient-space scan — 2 steps fused per iteration, exact algebra.
// 128 threads: thread (i,h) owns half h of row i (registers) and half of
// column i of Ccs. Per iteration (t0, t0+1):
//  phase 1: reload rows replaced last iter; sigA = C.p_t0, sigB = C.p_t0+1
//           (both over pre-replacement rows -> exact); write eA,eB,sigB. [bar]
//  phase 2: step A: dA -> invA -> cA. Step B scalar-patched: new-row score
//           = invA*sum(eA*sigB) -> e'; uB over updated Ccs + (e'-eB[slotA])*cA[i].
//           cA[i] is thread-local, so no second exchange. [bar]
// ---------------------------------------------------------------------------
__global__ __launch_bounds__(128, 1) void scan_kernel()
{
    __shared__ __align__(16) float p_buf[2][2][WIN];   // [parity][A/B][j]
    __shared__ __align__(16) float eA_sh[WIN];
    __shared__ __align__(16) float eB_sh[WIN];
    __shared__ __align__(16) float sB_sh[WIN];
    __shared__ __align__(16) float cnewA[WIN];
    __shared__ __align__(16) float cnewB[WIN];
    __shared__ __align__(16) float Ccs[WIN][68];       // Ccs[i][r] = C[r][i]

    const int b    = blockIdx.x;
    const int tid  = threadIdx.x;
    const int warp = tid >> 5;
    const int lane = tid & 31;
    const int h    = lane >> 4;                 // half 0/1
    const int i    = (lane & 15) | (warp << 4); // row & column index 0..63
    const int rb   = h << 5;                    // own half start

    // C = Identity
    uint64_t CrowP[16];
#pragma unroll
    for (int k = 0; k < 16; k++) {
        int j0 = rb + 2 * k;
        float x0 = (j0     == i) ? 1.f : 0.f;
        float x1 = (j0 + 1 == i) ? 1.f : 0.f;
        CrowP[k] = ((uint64_t)__float_as_uint(x1) << 32) | __float_as_uint(x0);
    }
    for (int r = rb; r < rb + 32; r++) Ccs[i][r] = (r == i) ? 1.f : 0.f;

    // Bootstrap: "rows replaced last iteration" are slots 62,63 with identity
    // rows, so the first reload is a no-op. Seed p parity-0 with p64,p65.
    if (h == 0) {
        cnewA[i] = (i == 62) ? 1.f : 0.f;
        cnewB[i] = (i == 63) ? 1.f : 0.f;
        p_buf[0][0][i] = g_P[((size_t)b * T_SEQ + WIN)     * WIN + i];
        p_buf[0][1][i] = g_P[((size_t)b * T_SEQ + WIN + 1) * WIN + i];
    }
    __syncthreads();

    float* gC = g_C + (size_t)b * T_SEQ * WIN;
    const float* gP = g_P + (size_t)b * T_SEQ * WIN;

    for (int t0 = WIN; t0 < T_SEQ; t0 += 2) {
        const int it  = (t0 - WIN) >> 1;
        const int cur = it & 1, nxt = cur ^ 1;
        const int slotPA = (t0 - 2) & (WIN - 1);
        const int slotPB = (t0 - 1) & (WIN - 1);
        const int slotA  = t0 & (WIN - 1);
        const int slotB  = (t0 + 1) & (WIN - 1);

        // ---- phase 1 ------------------------------------------------------
        // prefetch p_{t0+2}, p_{t0+3} for next iteration (consumed phase 2)
        float pnC = 0.f, pnD = 0.f;
        if (h == 0) {
            int tC = (t0 + 2 < T_SEQ) ? t0 + 2 : T_SEQ - 1;
            int tD = (t0 + 3 < T_SEQ) ? t0 + 3 : T_SEQ - 1;
            pnC = gP[(size_t)tC * WIN + i];
            pnD = gP[(size_t)tD * WIN + i];
        }

        // reload rows replaced last iteration
        if (i == slotPA) {
            const ulonglong2* cn = (const ulonglong2*)&cnewA[rb];
#pragma unroll
            for (int k = 0; k < 8; k++) {
                ulonglong2 v = cn[k];
                CrowP[2 * k] = v.x; CrowP[2 * k + 1] = v.y;
            }
        }
        if (i == slotPB) {
            const ulonglong2* cn = (const ulonglong2*)&cnewB[rb];
#pragma unroll
            for (int k = 0; k < 8; k++) {
                ulonglong2 v = cn[k];
                CrowP[2 * k] = v.x; CrowP[2 * k + 1] = v.y;
            }
        }

        // sigA = C_i . p_t0 ; sigB = C_i . p_{t0+1}  (own half, then shfl)
        const ulonglong2* pa = (const ulonglong2*)&p_buf[cur][0][rb];
        const ulonglong2* pb = (const ulonglong2*)&p_buf[cur][1][rb];
        uint64_t a0 = 0, a1 = 0, b0 = 0, b1 = 0;
#pragma unroll
        for (int k = 0; k < 8; k++) {
            ulonglong2 pva = pa[k];
            ulonglong2 pvb = pb[k];
            fma2(a0, CrowP[2 * k],     pva.x);
            fma2(a1, CrowP[2 * k + 1], pva.y);
            fma2(b0, CrowP[2 * k],     pvb.x);
            fma2(b1, CrowP[2 * k + 1], pvb.y);
        }
        add2(a0, a1); add2(b0, b1);
        float sigA = lo2(a0) + hi2(a0);
        float sigB = lo2(b0) + hi2(b0);
        sigA += __shfl_xor_sync(0xffffffffu, sigA, 16);
        sigB += __shfl_xor_sync(0xffffffffu, sigB, 16);
        const float eAo = ex2f(sigA);
        const float eBo = ex2f(sigB);
        if (h == 0) {
            eA_sh[i] = eAo;
            eB_sh[i] = eBo;
            sB_sh[i] = sigB;
        }
        __syncthreads();

        // ---- phase 2 ------------------------------------------------------
        // step A sums: dA = sum eA, uA = sum eA*Ccs, SAB = sum eA*sigB
        const ulonglong2* ev = (const ulonglong2*)&eA_sh[rb];
        const ulonglong2* sv = (const ulonglong2*)&sB_sh[rb];
        const ulonglong2* cv = (const ulonglong2*)&Ccs[i][rb];
        uint64_t dacc0 = 0, dacc1 = 0, uacc0 = 0, uacc1 = 0, sacc0 = 0, sacc1 = 0;
#pragma unroll
        for (int k = 0; k < 4; k++) {
            ulonglong2 e2a = ev[2 * k];
            ulonglong2 e2b = ev[2 * k + 1];
            ulonglong2 c2a = cv[2 * k];
            ulonglong2 c2b = cv[2 * k + 1];
            ulonglong2 s2a = sv[2 * k];
            ulonglong2 s2b = sv[2 * k + 1];
            add2(dacc0, e2a.x); add2(dacc1, e2a.y);
            add2(dacc0, e2b.x); add2(dacc1, e2b.y);
            fma2(uacc0, e2a.x, c2a.x); fma2(uacc1, e2a.y, c2a.y);
            fma2(uacc0, e2b.x, c2b.x); fma2(uacc1, e2b.y, c2b.y);
            fma2(sacc0, e2a.x, s2a.x); fma2(sacc1, e2a.y, s2a.y);
            fma2(sacc0, e2b.x, s2b.x); fma2(sacc1, e2b.y, s2b.y);
        }
        add2(dacc0, dacc1); add2(uacc0, uacc1); add2(sacc0, sacc1);
        float dA  = lo2(dacc0) + hi2(dacc0);
        float uA  = lo2(uacc0) + hi2(uacc0);
        float SAB = lo2(sacc0) + hi2(sacc0);
        dA  += __shfl_xor_sync(0xffffffffu, dA, 16);
        uA  += __shfl_xor_sync(0xffffffffu, uA, 16);
        SAB += __shfl_xor_sync(0xffffffffu, SAB, 16);

        const float invA = rcpf(dA + 1.f);
        const float cA_i = invA * uA;
        const float ePr  = ex2f(invA * SAB);   // exp(score of cA vs p_{t0+1})

        // commit cA (column write BEFORE uB full-sum; same-thread ordering)
        if ((slotA >> 5) == h) Ccs[i][slotA] = cA_i;
        const float eB_slotA = eB_sh[slotA];

        // step B sums over UPDATED Ccs (includes cA at slotA)
        const ulonglong2* ebv = (const ulonglong2*)&eB_sh[rb];
        uint64_t db0 = 0, db1 = 0, ub0 = 0, ub1 = 0;
#pragma unroll
        for (int k = 0; k < 4; k++) {
            ulonglong2 e2a = ebv[2 * k];
            ulonglong2 e2b = ebv[2 * k + 1];
            ulonglong2 c2a = ((const ulonglong2*)&Ccs[i][rb])[2 * k];
            ulonglong2 c2b = ((const ulonglong2*)&Ccs[i][rb])[2 * k + 1];
            add2(db0, e2a.x); add2(db1, e2a.y);
            add2(db0, e2b.x); add2(db1, e2b.y);
            fma2(ub0, e2a.x, c2a.x); fma2(ub1, e2a.y, c2a.y);
            fma2(ub0, e2b.x, c2b.x); fma2(ub1, e2b.y, c2b.y);
        }
        add2(db0, db1); add2(ub0, ub1);
        float dB = lo2(db0) + hi2(db0);
        float uB = lo2(ub0) + hi2(ub0);
        dB += __shfl_xor_sync(0xffffffffu, dB, 16);
        uB += __shfl_xor_sync(0xffffffffu, uB, 16);

        const float invB = rcpf(dB - eB_slotA + ePr + 1.f);
        const float cB_i = invB * (uB + (ePr - eB_slotA) * cA_i);

        if ((slotB >> 5) == h) Ccs[i][slotB] = cB_i;
        if (h == 0) {
            cnewA[i] = cA_i;
            cnewB[i] = cB_i;
            gC[(size_t)t0 * WIN + i]       = cA_i;
            gC[(size_t)(t0 + 1) * WIN + i] = cB_i;
            p_buf[nxt][0][i] = pnC;
            p_buf[nxt][1][i] = pnD;
        }
        __syncthreads();
    }
}

// ---------------------------------------------------------------------------
// k4: V[b] = C[b] (2048x64) @ F[b] (64x1024) -> d_out for t>=64.
// ---------------------------------------------------------------------------
__global__ __launch_bounds__(256) void v_kernel(
    const float* __restrict__ feat, float* __restrict__ out)
{
    __shared__ float Cst[64][68];
    __shared__ float Fs[64][64];
    const int b  = blockIdx.z;
    const int t0 = blockIdx.x * 64;
    const int d0 = blockIdx.y * 64;
    const int tid = threadIdx.x;
    const int ty = tid >> 4, tx = tid & 15;
    const int r0 = ty * 4, c0 = tx * 4;

#pragma unroll
    for (int l = 0; l < 4; l++) {
        int s = tid + l * 256;
        int r = s >> 4, j4 = (s & 15) * 4;
        float4 c = *(const float4*)(g_C + ((size_t)b * T_SEQ + t0 + r) * WIN + j4);
        Cst[j4 + 0][r] = c.x; Cst[j4 + 1][r] = c.y;
        Cst[j4 + 2][r] = c.z; Cst[j4 + 3][r] = c.w;
    }
#pragma unroll
    for (int l = 0; l < 4; l++) {
        int s = tid + l * 256;
        int j = s >> 4, c4 = (s & 15) * 4;
        *(float4*)&Fs[j][c4] =
            *(const float4*)(feat + ((size_t)b * T_SEQ + j) * DMODEL + d0 + c4);
    }
    __syncthreads();

    float acc[4][4];
#pragma unroll
    for (int i = 0; i < 4; i++)
#pragma unroll
        for (int j = 0; j < 4; j++) acc[i][j] = 0.f;

#pragma unroll 8
    for (int k = 0; k < 64; k++) {
        float a[4], bb[4];
        a[0] = Cst[k][r0]; a[1] = Cst[k][r0 + 1];
        a[2] = Cst[k][r0 + 2]; a[3] = Cst[k][r0 + 3];
        *(float4*)&bb[0] = *(float4*)&Fs[k][c0];
#pragma unroll
        for (int i = 0; i < 4; i++)
#pragma unroll
            for (int j = 0; j < 4; j++)
                acc[i][j] = fmaf(a[i], bb[j], acc[i][j]);
    }

#pragma unroll
    for (int i = 0; i < 4; i++) {
        int t = t0 + r0 + i;
        if (t >= WIN) {
            *(float4*)(out + ((size_t)b * T_SEQ + t) * DMODEL + d0 + c0) =
                make_float4(acc[i][0], acc[i][1], acc[i][2], acc[i][3]);
        }
    }
}

// ---------------------------------------------------------------------------
// k5: epilogue y = tanh(v)*f + f, LayerNorm.
// ---------------------------------------------------------------------------
__global__ __launch_bounds__(256) void ln_kernel(
    const float* __restrict__ feature, const float* __restrict__ g,
    const float* __restrict__ bt, float* __restrict__ out)
{
    const int row = blockIdx.x;
    const int t = row & (T_SEQ - 1);
    const float* fp = feature + (size_t)row * DMODEL;
    float* op = out + (size_t)row * DMODEL;
    const float* vp = (t < WIN) ? fp : op;
    const int tid = threadIdx.x;
    const int lane = tid & 31, warp = tid >> 5;

    float4 f = *(const float4*)(fp + tid * 4);
    float4 v = *(const float4*)(vp + tid * 4);
    float y0 = tanhf(v.x) * f.x + f.x;
    float y1 = tanhf(v.y) * f.y + f.y;
    float y2 = tanhf(v.z) * f.z + f.z;
    float y3 = tanhf(v.w) * f.w + f.w;

    float s  = y0 + y1 + y2 + y3;
    float ss = y0 * y0 + y1 * y1 + y2 * y2 + y3 * y3;
#pragma unroll
    for (int o = 16; o > 0; o >>= 1) {
        s  += __shfl_xor_sync(0xffffffffu, s, o);
        ss += __shfl_xor_sync(0xffffffffu, ss, o);
    }
    __shared__ float red[8][2];
    if (lane == 0) { red[warp][0] = s; red[warp][1] = ss; }
    __syncthreads();
    if (warp == 0) {
        float a = (lane < 8) ? red[lane][0] : 0.f;
        float c = (lane < 8) ? red[lane][1] : 0.f;
#pragma unroll
        for (int o = 4; o > 0; o >>= 1) {
            a += __shfl_xor_sync(0xffffffffu, a, o);
            c += __shfl_xor_sync(0xffffffffu, c, o);
        }
        if (lane == 0) { red[0][0] = a; red[0][1] = c; }
    }
    __syncthreads();
    const float mu   = red[0][0] * (1.f / DMODEL);
    const float var  = red[0][1] * (1.f / DMODEL) - mu * mu;
    const float rstd = rsqrtf(var + 1e-5f);

    float4 gg = *(const float4*)(g + tid * 4);
    float4 bb = *(const float4*)(bt + tid * 4);
    float4 o;
    o.x = (y0 - mu) * rstd * gg.x + bb.x;
    o.y = (y1 - mu) * rstd * gg.y + bb.y;
    o.z = (y2 - mu) * rstd * gg.z + bb.z;
    o.w = (y3 - mu) * rstd * gg.w + bb.w;
    *(float4*)(op + tid * 4) = o;
}

// ---------------------------------------------------------------------------
extern "C" void kernel_launch(void* const* d_in, const int* in_sizes, int n_in,
                              void* d_out, int out_size)
{
    const float* feature = (const float*)d_in[0];
    const float* wq_w    = (const float*)d_in[1];
    const float* wq_b    = (const float*)d_in[2];
    const float* w2_w    = (const float*)d_in[3];
    // d_in[4] = w2_b: cancels by softmax shift-invariance
    const float* ln_g    = (const float*)d_in[5];
    const float* ln_b    = (const float*)d_in[6];
    float* out = (float*)d_out;

    bias_p_kernel<<<BATCH, 256>>>(feature, wq_b, w2_w);
    m_kernel<<<dim3(8, BATCH), 256>>>(wq_w, w2_w, feature);
    p_kernel<<<dim3(16, BATCH), 256>>>(feature);
    scan_kernel<<<BATCH, 128>>>();
    v_kernel<<<dim3(32, 16, BATCH), 256>>>(feature, out);
    ln_kernel<<<BATCH * T_SEQ, 256>>>(feature, ln_g, ln_b, out);
}